// round 13
// baseline (speedup 1.0000x reference)
#include <cuda_runtime.h>
#include <cuda_fp16.h>
#include <cstdint>

#define MROWS 32768
#define NQ 3
#define NE 256
#define ED 32
#define CBPAD 33

#define LO_SCALE 4096.0f
#define LO_INV   (1.0f / 4096.0f)

// ---------------- scratch ----------------
__device__ float g_loss;
__device__ float g_h2f[(size_t)MROWS * 128];
__device__ float g_lat[(size_t)MROWS * ED];
__device__ __half g_x_hi [(size_t)MROWS * 1024];
__device__ __half g_x_lo [(size_t)MROWS * 1024];
__device__ __half g_h0_hi[(size_t)MROWS * 512];
__device__ __half g_h0_lo[(size_t)MROWS * 512];
__device__ __half g_h1_hi[(size_t)MROWS * 256];
__device__ __half g_h1_lo[(size_t)MROWS * 256];
__device__ __half g_xq_hi[(size_t)MROWS * ED];
__device__ __half g_xq_lo[(size_t)MROWS * ED];
__device__ __half g_g0_hi[(size_t)MROWS * 128];
__device__ __half g_g0_lo[(size_t)MROWS * 128];
__device__ __half g_g1_hi[(size_t)MROWS * 256];
__device__ __half g_g1_lo[(size_t)MROWS * 256];
__device__ __half g_g2_hi[(size_t)MROWS * 512];
__device__ __half g_g2_lo[(size_t)MROWS * 512];
#define WOFF0 0
#define WOFF1 (WOFF0 + 512*1024)
#define WOFF2 (WOFF1 + 256*512)
#define WOFF3 (WOFF2 + 128*256)
#define WOFF4 (WOFF3 + 128*32)
#define WOFF5 (WOFF4 + 256*128)
#define WOFF6 (WOFF5 + 512*256)
#define WTOT  (WOFF6 + 1024*512)
__device__ __half g_w_hi[WTOT];
__device__ __half g_w_lo[WTOT];

__device__ __forceinline__ void mma_f16(float* c,
    uint32_t a0, uint32_t a1, uint32_t a2, uint32_t a3, uint32_t b0, uint32_t b1) {
    asm volatile(
        "mma.sync.aligned.m16n8k16.row.col.f32.f16.f16.f32 "
        "{%0,%1,%2,%3}, {%4,%5,%6,%7}, {%8,%9}, {%0,%1,%2,%3};"
        : "+f"(c[0]), "+f"(c[1]), "+f"(c[2]), "+f"(c[3])
        : "r"(a0), "r"(a1), "r"(a2), "r"(a3), "r"(b0), "r"(b1));
}

// fp16-accumulator MMA for the low-order correction term
__device__ __forceinline__ void mma_f16acc(uint32_t* c,
    uint32_t a0, uint32_t a1, uint32_t a2, uint32_t a3, uint32_t b0, uint32_t b1) {
    asm volatile(
        "mma.sync.aligned.m16n8k16.row.col.f16.f16.f16.f16 "
        "{%0,%1}, {%2,%3,%4,%5}, {%6,%7}, {%0,%1};"
        : "+r"(c[0]), "+r"(c[1])
        : "r"(a0), "r"(a1), "r"(a2), "r"(a3), "r"(b0), "r"(b1));
}

__device__ __forceinline__ void ldmatrix_x4(uint32_t& r0, uint32_t& r1,
                                            uint32_t& r2, uint32_t& r3, uint32_t addr) {
    asm volatile("ldmatrix.sync.aligned.m8n8.x4.shared.b16 {%0,%1,%2,%3}, [%4];"
                 : "=r"(r0), "=r"(r1), "=r"(r2), "=r"(r3) : "r"(addr));
}

__device__ __forceinline__ uint32_t pack2(__half a, __half b) {
    return (uint32_t)__half_as_ushort(a) | ((uint32_t)__half_as_ushort(b) << 16);
}

__device__ __forceinline__ void split_pack(float x0, float x1, uint32_t& hi, uint32_t& lo) {
    __half h0 = __float2half_rn(x0);
    __half h1 = __float2half_rn(x1);
    __half l0 = __float2half_rn((x0 - __half2float(h0)) * LO_SCALE);
    __half l1 = __float2half_rn((x1 - __half2float(h1)) * LO_SCALE);
    hi = pack2(h0, h1);
    lo = pack2(l0, l1);
}

__device__ __forceinline__ float lo_half(uint32_t u) {
    return __half2float(__ushort_as_half((unsigned short)(u & 0xFFFFu)));
}
__device__ __forceinline__ float hi_half(uint32_t u) {
    return __half2float(__ushort_as_half((unsigned short)(u >> 16)));
}

__device__ __forceinline__ void cp_async16(uint32_t smem_addr, const void* gptr) {
    asm volatile("cp.async.cg.shared.global [%0], [%1], 16;" :: "r"(smem_addr), "l"(gptr));
}
__device__ __forceinline__ void cp_commit() {
    asm volatile("cp.async.commit_group;" ::: "memory");
}
template<int N>
__device__ __forceinline__ void cp_wait() {
    asm volatile("cp.async.wait_group %0;" :: "n"(N) : "memory");
}

// ---------------- generic fp32 -> split kernel ----------------
__global__ void split_kernel(const float* __restrict__ src, __half* __restrict__ hi,
                             __half* __restrict__ lo, int n4) {
    int i = blockIdx.x * blockDim.x + threadIdx.x;
    if (i >= n4) return;
    float4 v = ((const float4*)src)[i];
    uint32_t h0, l0, h1, l1;
    split_pack(v.x, v.y, h0, l0);
    split_pack(v.z, v.w, h1, l1);
    uint2 hv; hv.x = h0; hv.y = h1;
    uint2 lv; lv.x = l0; lv.y = l1;
    ((uint2*)hi)[i] = hv;
    ((uint2*)lo)[i] = lv;
}

// ---------------- HMMA fp16-split GEMM, 3-stage cp.async + ldmatrix ----------------
// acc1 (fp32) = hi*hi ; acc2 (fp16) = hi*lo' + lo'*hi. C = acc1 + acc2*2^-12 + bias.
#define HPITCH 20
#define SM_A_HI 0
#define SM_A_LO (128 * HPITCH)
#define SM_B_HI (256 * HPITCH)
#define SM_B_LO (320 * HPITCH)
#define SM_WORDS (384 * HPITCH)
#define NSTAGE 3
#define SMEM_BYTES_GEMM (NSTAGE * SM_WORDS * 4)

template<bool RELU, bool OUTF32>
__global__ void __launch_bounds__(256, 2)
gemm_split_kernel(const __half* __restrict__ Ahi, const __half* __restrict__ Alo,
                  const __half* __restrict__ Whi, const __half* __restrict__ Wlo,
                  const float* __restrict__ bias,
                  __half* __restrict__ Chi, __half* __restrict__ Clo,
                  float* __restrict__ Cf,
                  int N, int K)
{
    extern __shared__ uint32_t sm[];
    uint32_t sbase;
    asm("{ .reg .u64 t; cvta.to.shared.u64 t, %1; cvt.u32.u64 %0, t; }"
        : "=r"(sbase) : "l"((const void*)sm));

    const int tid = threadIdx.x;
    const int bn = blockIdx.x * 64;
    const int bm = blockIdx.y * 128;
    const int w = tid >> 5, lane = tid & 31;
    const int wm = (w & 3) * 32;
    const int wn = (w >> 2) * 32;
    const int qr = lane >> 2;
    const int qc = lane & 3;
    const int jj = lane >> 3, rr = lane & 7;

    float acc1[2][4][4];
    uint32_t acc2[2][4][2];
    #pragma unroll
    for (int i = 0; i < 2; i++)
        #pragma unroll
        for (int j = 0; j < 4; j++) {
            #pragma unroll
            for (int k = 0; k < 4; k++) acc1[i][j][k] = 0.f;
            acc2[i][j][0] = 0u; acc2[i][j][1] = 0u;
        }

    const int nk = K >> 5;
    const int ra = tid >> 2;
    const int c4 = tid & 3;

    auto prefetch = [&](int ck, int buf) {
        const uint32_t sb = sbase + buf * (SM_WORDS * 4);
        #pragma unroll
        for (int i = 0; i < 2; i++) {
            const int r = ra + i * 64;
            const size_t go = (size_t)(bm + r) * K + ck * 32 + c4 * 8;
            cp_async16(sb + (SM_A_HI + r * HPITCH + c4 * 4) * 4, Ahi + go);
            cp_async16(sb + (SM_A_LO + r * HPITCH + c4 * 4) * 4, Alo + go);
        }
        {
            const int r = ra;
            const size_t go = (size_t)(bn + r) * K + ck * 32 + c4 * 8;
            cp_async16(sb + (SM_B_HI + r * HPITCH + c4 * 4) * 4, Whi + go);
            cp_async16(sb + (SM_B_LO + r * HPITCH + c4 * 4) * 4, Wlo + go);
        }
        cp_commit();
    };

    prefetch(0, 0);
    if (nk > 1) prefetch(1, 1);

    const int a_m  = ((jj & 1) << 3) + rr;
    const int a_kw = (jj >> 1) << 2;
    const int b_n  = rr;
    const int b_kw = jj << 2;

    int buf = 0;
    for (int ck = 0; ck < nk; ck++) {
        if (ck == nk - 1) cp_wait<0>(); else cp_wait<1>();
        __syncthreads();
        if (ck + 2 < nk) prefetch(ck + 2, (buf + 2) % NSTAGE);

        const uint32_t bufb = sbase + buf * (SM_WORDS * 4);

        uint32_t ah[2][2][4], al[2][2][4];
        #pragma unroll
        for (int mt = 0; mt < 2; mt++)
            #pragma unroll
            for (int ks = 0; ks < 2; ks++) {
                const uint32_t wo = (uint32_t)((wm + mt * 16 + a_m) * HPITCH + ks * 8 + a_kw);
                ldmatrix_x4(ah[mt][ks][0], ah[mt][ks][1], ah[mt][ks][2], ah[mt][ks][3],
                            bufb + (SM_A_HI + wo) * 4);
                ldmatrix_x4(al[mt][ks][0], al[mt][ks][1], al[mt][ks][2], al[mt][ks][3],
                            bufb + (SM_A_LO + wo) * 4);
            }

        #pragma unroll
        for (int nt = 0; nt < 4; nt++) {
            const uint32_t wo = (uint32_t)((wn + nt * 8 + b_n) * HPITCH + b_kw);
            uint32_t bh[2][2], bl[2][2];
            ldmatrix_x4(bh[0][0], bh[0][1], bh[1][0], bh[1][1], bufb + (SM_B_HI + wo) * 4);
            #pragma unroll
            for (int ks = 0; ks < 2; ks++) {
                #pragma unroll
                for (int mt = 0; mt < 2; mt++)
                    mma_f16(acc1[mt][nt], ah[mt][ks][0], ah[mt][ks][1],
                            ah[mt][ks][2], ah[mt][ks][3], bh[ks][0], bh[ks][1]);
                #pragma unroll
                for (int mt = 0; mt < 2; mt++)
                    mma_f16acc(acc2[mt][nt], al[mt][ks][0], al[mt][ks][1],
                               al[mt][ks][2], al[mt][ks][3], bh[ks][0], bh[ks][1]);
            }
            ldmatrix_x4(bl[0][0], bl[0][1], bl[1][0], bl[1][1], bufb + (SM_B_LO + wo) * 4);
            #pragma unroll
            for (int ks = 0; ks < 2; ks++)
                #pragma unroll
                for (int mt = 0; mt < 2; mt++)
                    mma_f16acc(acc2[mt][nt], ah[mt][ks][0], ah[mt][ks][1],
                               ah[mt][ks][2], ah[mt][ks][3], bl[ks][0], bl[ks][1]);
        }
        buf++; if (buf == NSTAGE) buf = 0;
    }

    // ---- epilogue ----
    #pragma unroll
    for (int nt = 0; nt < 4; nt++) {
        const int col = bn + wn + nt * 8 + qc * 2;
        const float b0 = bias[col], b1 = bias[col + 1];
        #pragma unroll
        for (int mt = 0; mt < 2; mt++) {
            const int row = bm + wm + mt * 16 + qr;
            const uint32_t p0 = acc2[mt][nt][0], p1 = acc2[mt][nt][1];
            float2 v0, v1;
            v0.x = fmaf(lo_half(p0), LO_INV, acc1[mt][nt][0]) + b0;
            v0.y = fmaf(hi_half(p0), LO_INV, acc1[mt][nt][1]) + b1;
            v1.x = fmaf(lo_half(p1), LO_INV, acc1[mt][nt][2]) + b0;
            v1.y = fmaf(hi_half(p1), LO_INV, acc1[mt][nt][3]) + b1;
            if (RELU) {
                v0.x = fmaxf(v0.x, 0.f); v0.y = fmaxf(v0.y, 0.f);
                v1.x = fmaxf(v1.x, 0.f); v1.y = fmaxf(v1.y, 0.f);
            }
            if (OUTF32) {
                *(float2*)(Cf + (size_t)row * N + col) = v0;
                *(float2*)(Cf + (size_t)(row + 8) * N + col) = v1;
            } else {
                uint32_t h, l;
                split_pack(v0.x, v0.y, h, l);
                ((uint32_t*)Chi)[((size_t)row * N + col) >> 1] = h;
                ((uint32_t*)Clo)[((size_t)row * N + col) >> 1] = l;
                split_pack(v1.x, v1.y, h, l);
                ((uint32_t*)Chi)[((size_t)(row + 8) * N + col) >> 1] = h;
                ((uint32_t*)Clo)[((size_t)(row + 8) * N + col) >> 1] = l;
            }
        }
    }
}

// ---------------- SIMT fp32 GEMM (N=32 latent layer) ----------------
template<int BM, int BN, int BK, int TM, int TN, bool RELU>
__global__ void __launch_bounds__((BM/TM)*(BN/TN))
gemm_nt_kernel(const float* __restrict__ A, const float* __restrict__ W,
               const float* __restrict__ bias, float* __restrict__ C,
               int M, int N, int K)
{
    constexpr int THREADS = (BM/TM)*(BN/TN);
    __shared__ float As[BK][BM];
    __shared__ float Ws[BK][BN];

    const int bm = blockIdx.y * BM;
    const int bn = blockIdx.x * BN;
    const int tid = threadIdx.x;
    const int tn = (tid % (BN/TN)) * TN;
    const int tm = (tid / (BN/TN)) * TM;

    float acc[TM][TN];
    #pragma unroll
    for (int i = 0; i < TM; i++)
        #pragma unroll
        for (int j = 0; j < TN; j++) acc[i][j] = 0.f;

    for (int k0 = 0; k0 < K; k0 += BK) {
        constexpr int A_LOADS = (BM*BK) / (4*THREADS);
        #pragma unroll
        for (int i = 0; i < A_LOADS; i++) {
            int idx = (tid + i*THREADS) * 4;
            int r = idx / BK, c = idx % BK;
            float4 v = *(const float4*)(A + (size_t)(bm + r)*K + k0 + c);
            As[c+0][r] = v.x; As[c+1][r] = v.y; As[c+2][r] = v.z; As[c+3][r] = v.w;
        }
        constexpr int W_LOADS = (BN*BK) / (4*THREADS);
        #pragma unroll
        for (int i = 0; i < W_LOADS; i++) {
            int idx = (tid + i*THREADS) * 4;
            int r = idx / BK, c = idx % BK;
            float4 v = *(const float4*)(W + (size_t)(bn + r)*K + k0 + c);
            Ws[c+0][r] = v.x; Ws[c+1][r] = v.y; Ws[c+2][r] = v.z; Ws[c+3][r] = v.w;
        }
        __syncthreads();

        #pragma unroll
        for (int k = 0; k < BK; k++) {
            float ar[TM], wr[TN];
            #pragma unroll
            for (int i = 0; i < TM; i += 4) {
                float4 v = *(const float4*)(&As[k][tm + i]);
                ar[i+0] = v.x; ar[i+1] = v.y; ar[i+2] = v.z; ar[i+3] = v.w;
            }
            #pragma unroll
            for (int j = 0; j < TN; j += 4) {
                float4 v = *(const float4*)(&Ws[k][tn + j]);
                wr[j+0] = v.x; wr[j+1] = v.y; wr[j+2] = v.z; wr[j+3] = v.w;
            }
            #pragma unroll
            for (int i = 0; i < TM; i++)
                #pragma unroll
                for (int j = 0; j < TN; j++)
                    acc[i][j] = fmaf(ar[i], wr[j], acc[i][j]);
        }
        __syncthreads();
    }

    #pragma unroll
    for (int i = 0; i < TM; i++)
        #pragma unroll
        for (int j = 0; j < TN; j++) {
            float v = acc[i][j] + bias[bn + tn + j];
            if (RELU) v = fmaxf(v, 0.f);
            C[(size_t)(bm + tm + i)*N + bn + tn + j] = v;
        }
}

// ---------------- fused residual-VQ kernel (warp-shuffle argmin) ----------------
__global__ void __launch_bounds__(NE)
vq_kernel(const float* __restrict__ latent,
          const float* __restrict__ cb0, const float* __restrict__ cb1,
          const float* __restrict__ cb2,
          __half* __restrict__ xq_hi, __half* __restrict__ xq_lo,
          float* __restrict__ out_idx, float* __restrict__ out_oh,
          float* __restrict__ out_logits,
          int rows_per_block)
{
    extern __shared__ float smf[];
    float* cbs    = smf;
    float* cnorm  = cbs + NQ*NE*CBPAD;
    float* resid  = cnorm + NQ*NE;
    float* xqrow  = resid + ED;
    float* warp_v = xqrow + ED;
    int*   warp_i = (int*)(warp_v + 8);
    int*   s_best = warp_i + 8;

    const int t = threadIdx.x;
    const int wid = t >> 5, lane = t & 31;

    const float* srcs[NQ] = {cb0, cb1, cb2};
    for (int q = 0; q < NQ; q++)
        for (int i = t; i < NE*ED; i += NE) {
            int r = i / ED, c = i % ED;
            cbs[(q*NE + r)*CBPAD + c] = srcs[q][i];
        }
    __syncthreads();
    for (int q = 0; q < NQ; q++) {
        const float* row = &cbs[(q*NE + t)*CBPAD];
        float s = 0.f;
        #pragma unroll
        for (int k = 0; k < ED; k++) s = fmaf(row[k], row[k], s);
        cnorm[q*NE + t] = s;
    }
    __syncthreads();

    float loss_acc = 0.f;
    const int row0 = blockIdx.x * rows_per_block;
    const int row1 = min(row0 + rows_per_block, MROWS);

    for (int r = row0; r < row1; r++) {
        if (t < ED) { resid[t] = latent[(size_t)r*ED + t]; xqrow[t] = 0.f; }
        __syncthreads();

        for (int q = 0; q < NQ; q++) {
            const float* crow = &cbs[(q*NE + t)*CBPAD];
            float dot = 0.f, rn = 0.f;
            #pragma unroll
            for (int k = 0; k < ED; k++) {
                float rv = resid[k];
                dot = fmaf(rv, crow[k], dot);
                rn  = fmaf(rv, rv, rn);
            }
            float d = rn + cnorm[q*NE + t] - 2.f*dot;
            out_logits[((size_t)r*NQ + q)*NE + t] = d;

            float bv = d; int bi = t;
            #pragma unroll
            for (int o = 16; o; o >>= 1) {
                float ov = __shfl_xor_sync(0xffffffffu, bv, o);
                int   oi = __shfl_xor_sync(0xffffffffu, bi, o);
                if (ov < bv || (ov == bv && oi < bi)) { bv = ov; bi = oi; }
            }
            if (lane == 0) { warp_v[wid] = bv; warp_i[wid] = bi; }
            __syncthreads();
            if (t < 8) {
                bv = warp_v[t]; bi = warp_i[t];
                #pragma unroll
                for (int o = 4; o; o >>= 1) {
                    float ov = __shfl_xor_sync(0xffu, bv, o, 8);
                    int   oi = __shfl_xor_sync(0xffu, bi, o, 8);
                    if (ov < bv || (ov == bv && oi < bi)) { bv = ov; bi = oi; }
                }
                if (t == 0) s_best[0] = bi;
            }
            __syncthreads();
            const int best = s_best[0];

            out_oh[((size_t)r*NQ + q)*NE + t] = (t == best) ? 1.f : 0.f;
            if (t == 0) out_idx[(size_t)r*NQ + q] = (float)best;

            if (t < 32) {
                float c  = cbs[(q*NE + best)*CBPAD + t];
                float rv = resid[t];
                float diff = c - rv;
                float xres = rv + diff;
                float sq = diff*diff;
                #pragma unroll
                for (int o = 16; o; o >>= 1) sq += __shfl_xor_sync(0xffffffffu, sq, o);
                if (t == 0) loss_acc += sq;
                resid[t] = rv - xres;
                xqrow[t] += xres;
            }
            __syncthreads();
        }
        if (t < ED/2) {
            float x0 = xqrow[2*t], x1 = xqrow[2*t + 1];
            uint32_t h, l;
            split_pack(x0, x1, h, l);
            ((uint32_t*)xq_hi)[(size_t)r * (ED/2) + t] = h;
            ((uint32_t*)xq_lo)[(size_t)r * (ED/2) + t] = l;
        }
        __syncthreads();
    }
    if (t == 0) atomicAdd(&g_loss, loss_acc);
}

__global__ void zero_loss_kernel() { g_loss = 0.f; }

__global__ void finalize_kernel(float* __restrict__ loss_out)
{
    loss_out[0] = g_loss * (1.25f / (3.0f * (float)MROWS * (float)ED));
}

// ---------------- launch ----------------
extern "C" void kernel_launch(void* const* d_in, const int* in_sizes, int n_in,
                              void* d_out, int out_size)
{
    const float* x   = (const float*)d_in[0];
    const float* ew[4] = {(const float*)d_in[1], (const float*)d_in[3],
                          (const float*)d_in[5], (const float*)d_in[7]};
    const float* eb[4] = {(const float*)d_in[2], (const float*)d_in[4],
                          (const float*)d_in[6], (const float*)d_in[8]};
    const float* dw[4] = {(const float*)d_in[9],  (const float*)d_in[11],
                          (const float*)d_in[13], (const float*)d_in[15]};
    const float* db[4] = {(const float*)d_in[10], (const float*)d_in[12],
                          (const float*)d_in[14], (const float*)d_in[16]};
    const float* cb0 = (const float*)d_in[17];
    const float* cb1 = (const float*)d_in[18];
    const float* cb2 = (const float*)d_in[19];
    float* out = (float*)d_out;

    float *h2f, *lat;
    cudaGetSymbolAddress((void**)&h2f, g_h2f);
    cudaGetSymbolAddress((void**)&lat, g_lat);
    __half *xhi, *xlo, *h0hi, *h0lo, *h1hi, *h1lo, *xqhi, *xqlo;
    __half *g0hi, *g0lo, *g1hi, *g1lo, *g2hi, *g2lo, *whi, *wlo;
    cudaGetSymbolAddress((void**)&xhi,  g_x_hi);  cudaGetSymbolAddress((void**)&xlo,  g_x_lo);
    cudaGetSymbolAddress((void**)&h0hi, g_h0_hi); cudaGetSymbolAddress((void**)&h0lo, g_h0_lo);
    cudaGetSymbolAddress((void**)&h1hi, g_h1_hi); cudaGetSymbolAddress((void**)&h1lo, g_h1_lo);
    cudaGetSymbolAddress((void**)&xqhi, g_xq_hi); cudaGetSymbolAddress((void**)&xqlo, g_xq_lo);
    cudaGetSymbolAddress((void**)&g0hi, g_g0_hi); cudaGetSymbolAddress((void**)&g0lo, g_g0_lo);
    cudaGetSymbolAddress((void**)&g1hi, g_g1_hi); cudaGetSymbolAddress((void**)&g1lo, g_g1_lo);
    cudaGetSymbolAddress((void**)&g2hi, g_g2_hi); cudaGetSymbolAddress((void**)&g2lo, g_g2_lo);
    cudaGetSymbolAddress((void**)&whi,  g_w_hi);  cudaGetSymbolAddress((void**)&wlo,  g_w_lo);

    const size_t OFF_OUT  = 0;
    const size_t OFF_LOSS = (size_t)MROWS * 1024;
    const size_t OFF_IDX  = OFF_LOSS + 1;
    const size_t OFF_OH   = OFF_IDX + (size_t)MROWS * NQ;
    const size_t OFF_LG   = OFF_OH  + (size_t)MROWS * NQ * NE;

    cudaFuncSetAttribute(gemm_split_kernel<true,false>, cudaFuncAttributeMaxDynamicSharedMemorySize, SMEM_BYTES_GEMM);
    cudaFuncSetAttribute(gemm_split_kernel<true,true>,  cudaFuncAttributeMaxDynamicSharedMemorySize, SMEM_BYTES_GEMM);
    cudaFuncSetAttribute(gemm_split_kernel<false,true>, cudaFuncAttributeMaxDynamicSharedMemorySize, SMEM_BYTES_GEMM);

    const int MT = MROWS / 128;
    auto splitN = [](int n) { return (n / 4 + 255) / 256; };

    // pre-split inputs + weights
    split_kernel<<<splitN(MROWS*1024), 256>>>(x, xhi, xlo, MROWS*1024/4);
    split_kernel<<<splitN(512*1024), 256>>>(ew[0], whi + WOFF0, wlo + WOFF0, 512*1024/4);
    split_kernel<<<splitN(256*512),  256>>>(ew[1], whi + WOFF1, wlo + WOFF1, 256*512/4);
    split_kernel<<<splitN(128*256),  256>>>(ew[2], whi + WOFF2, wlo + WOFF2, 128*256/4);
    split_kernel<<<splitN(128*32),   256>>>(dw[0], whi + WOFF3, wlo + WOFF3, 128*32/4);
    split_kernel<<<splitN(256*128),  256>>>(dw[1], whi + WOFF4, wlo + WOFF4, 256*128/4);
    split_kernel<<<splitN(512*256),  256>>>(dw[2], whi + WOFF5, wlo + WOFF5, 512*256/4);
    split_kernel<<<splitN(1024*512), 256>>>(dw[3], whi + WOFF6, wlo + WOFF6, 1024*512/4);

    // encoder
    gemm_split_kernel<true,false><<<dim3(8, MT), 256, SMEM_BYTES_GEMM>>>(
        xhi, xlo, whi + WOFF0, wlo + WOFF0, eb[0], h0hi, h0lo, nullptr, 512, 1024);
    gemm_split_kernel<true,false><<<dim3(4, MT), 256, SMEM_BYTES_GEMM>>>(
        h0hi, h0lo, whi + WOFF1, wlo + WOFF1, eb[1], h1hi, h1lo, nullptr, 256, 512);
    gemm_split_kernel<true,true><<<dim3(2, MT), 256, SMEM_BYTES_GEMM>>>(
        h1hi, h1lo, whi + WOFF2, wlo + WOFF2, eb[2], nullptr, nullptr, h2f, 128, 256);
    gemm_nt_kernel<128, 32,16,8,4,false><<<dim3(1, MT), 128>>>(h2f, ew[3], eb[3], lat, MROWS, 32, 128);

    // residual VQ
    zero_loss_kernel<<<1,1>>>();
    const size_t vq_smem = (size_t)(NQ*NE*CBPAD + NQ*NE + 2*ED + 8)*4 + 8*4 + 4;
    cudaFuncSetAttribute(vq_kernel, cudaFuncAttributeMaxDynamicSharedMemorySize, (int)vq_smem);
    vq_kernel<<<MROWS/32, NE, vq_smem>>>(lat, cb0, cb1, cb2, xqhi, xqlo,
                                         out + OFF_IDX, out + OFF_OH, out + OFF_LG, 32);
    finalize_kernel<<<1,1>>>(out + OFF_LOSS);

    // decoder
    gemm_split_kernel<true,false><<<dim3(2,  MT), 256, SMEM_BYTES_GEMM>>>(
        xqhi, xqlo, whi + WOFF3, wlo + WOFF3, db[0], g0hi, g0lo, nullptr, 128, 32);
    gemm_split_kernel<true,false><<<dim3(4,  MT), 256, SMEM_BYTES_GEMM>>>(
        g0hi, g0lo, whi + WOFF4, wlo + WOFF4, db[1], g1hi, g1lo, nullptr, 256, 128);
    gemm_split_kernel<true,false><<<dim3(8,  MT), 256, SMEM_BYTES_GEMM>>>(
        g1hi, g1lo, whi + WOFF5, wlo + WOFF5, db[2], g2hi, g2lo, nullptr, 512, 256);
    gemm_split_kernel<false,true><<<dim3(16, MT), 256, SMEM_BYTES_GEMM>>>(
        g2hi, g2lo, whi + WOFF6, wlo + WOFF6, db[3], nullptr, nullptr, out + OFF_OUT, 1024, 512);
}

// round 16
// speedup vs baseline: 1.1686x; 1.1686x over previous
#include <cuda_runtime.h>
#include <cuda_fp16.h>
#include <cstdint>

#define MROWS 32768
#define NQ 3
#define NE 256
#define ED 32
#define CBPAD 33

#define LO_SCALE 4096.0f
#define LO_INV   (1.0f / 4096.0f)

// ---------------- scratch ----------------
__device__ float g_loss;
__device__ float g_h2f[(size_t)MROWS * 128];
__device__ float g_lat[(size_t)MROWS * ED];
__device__ __half g_x_hi [(size_t)MROWS * 1024];
__device__ __half g_x_lo [(size_t)MROWS * 1024];
__device__ __half g_h0_hi[(size_t)MROWS * 512];
__device__ __half g_h0_lo[(size_t)MROWS * 512];
__device__ __half g_h1_hi[(size_t)MROWS * 256];
__device__ __half g_h1_lo[(size_t)MROWS * 256];
__device__ __half g_xq_hi[(size_t)MROWS * ED];
__device__ __half g_xq_lo[(size_t)MROWS * ED];
__device__ __half g_g0_hi[(size_t)MROWS * 128];
__device__ __half g_g0_lo[(size_t)MROWS * 128];
__device__ __half g_g1_hi[(size_t)MROWS * 256];
__device__ __half g_g1_lo[(size_t)MROWS * 256];
__device__ __half g_g2_hi[(size_t)MROWS * 512];
__device__ __half g_g2_lo[(size_t)MROWS * 512];
#define WOFF0 0
#define WOFF1 (WOFF0 + 512*1024)
#define WOFF2 (WOFF1 + 256*512)
#define WOFF3 (WOFF2 + 128*256)
#define WOFF4 (WOFF3 + 128*32)
#define WOFF5 (WOFF4 + 256*128)
#define WOFF6 (WOFF5 + 512*256)
#define WTOT  (WOFF6 + 1024*512)
__device__ __half g_w_hi[WTOT];
__device__ __half g_w_lo[WTOT];

__device__ __forceinline__ void mma_f16(float* c,
    uint32_t a0, uint32_t a1, uint32_t a2, uint32_t a3, uint32_t b0, uint32_t b1) {
    asm volatile(
        "mma.sync.aligned.m16n8k16.row.col.f32.f16.f16.f32 "
        "{%0,%1,%2,%3}, {%4,%5,%6,%7}, {%8,%9}, {%0,%1,%2,%3};"
        : "+f"(c[0]), "+f"(c[1]), "+f"(c[2]), "+f"(c[3])
        : "r"(a0), "r"(a1), "r"(a2), "r"(a3), "r"(b0), "r"(b1));
}

__device__ __forceinline__ void ldmatrix_x4(uint32_t& r0, uint32_t& r1,
                                            uint32_t& r2, uint32_t& r3, uint32_t addr) {
    asm volatile("ldmatrix.sync.aligned.m8n8.x4.shared.b16 {%0,%1,%2,%3}, [%4];"
                 : "=r"(r0), "=r"(r1), "=r"(r2), "=r"(r3) : "r"(addr));
}

__device__ __forceinline__ uint32_t pack2(__half a, __half b) {
    return (uint32_t)__half_as_ushort(a) | ((uint32_t)__half_as_ushort(b) << 16);
}

__device__ __forceinline__ void split_pack(float x0, float x1, uint32_t& hi, uint32_t& lo) {
    __half h0 = __float2half_rn(x0);
    __half h1 = __float2half_rn(x1);
    __half l0 = __float2half_rn((x0 - __half2float(h0)) * LO_SCALE);
    __half l1 = __float2half_rn((x1 - __half2float(h1)) * LO_SCALE);
    hi = pack2(h0, h1);
    lo = pack2(l0, l1);
}

__device__ __forceinline__ void cp_async16(uint32_t smem_addr, const void* gptr) {
    asm volatile("cp.async.cg.shared.global [%0], [%1], 16;" :: "r"(smem_addr), "l"(gptr));
}
__device__ __forceinline__ void cp_commit() {
    asm volatile("cp.async.commit_group;" ::: "memory");
}
template<int N>
__device__ __forceinline__ void cp_wait() {
    asm volatile("cp.async.wait_group %0;" :: "n"(N) : "memory");
}

// ---------------- generic fp32 -> split kernel ----------------
__global__ void split_kernel(const float* __restrict__ src, __half* __restrict__ hi,
                             __half* __restrict__ lo, int n4) {
    int i = blockIdx.x * blockDim.x + threadIdx.x;
    if (i >= n4) return;
    float4 v = ((const float4*)src)[i];
    uint32_t h0, l0, h1, l1;
    split_pack(v.x, v.y, h0, l0);
    split_pack(v.z, v.w, h1, l1);
    uint2 hv; hv.x = h0; hv.y = h1;
    uint2 lv; lv.x = l0; lv.y = l1;
    ((uint2*)hi)[i] = hv;
    ((uint2*)lo)[i] = lv;
}

// ---------------- HMMA fp16-split GEMM, 3-stage cp.async + ldmatrix ----------------
// acc1 = hi*hi ; acc2 = hi*lo' + lo'*hi. C = acc1 + acc2*2^-12 + bias.
#define HPITCH 20
#define SM_A_HI 0
#define SM_A_LO (128 * HPITCH)
#define SM_B_HI (256 * HPITCH)
#define SM_B_LO (320 * HPITCH)
#define SM_WORDS (384 * HPITCH)
#define NSTAGE 3
#define SMEM_BYTES_GEMM (NSTAGE * SM_WORDS * 4)

template<bool RELU, bool OUTF32>
__global__ void __launch_bounds__(256, 2)
gemm_split_kernel(const __half* __restrict__ Ahi, const __half* __restrict__ Alo,
                  const __half* __restrict__ Whi, const __half* __restrict__ Wlo,
                  const float* __restrict__ bias,
                  __half* __restrict__ Chi, __half* __restrict__ Clo,
                  float* __restrict__ Cf,
                  int N, int K)
{
    extern __shared__ uint32_t sm[];
    uint32_t sbase;
    asm("{ .reg .u64 t; cvta.to.shared.u64 t, %1; cvt.u32.u64 %0, t; }"
        : "=r"(sbase) : "l"((const void*)sm));

    const int tid = threadIdx.x;
    const int bn = blockIdx.x * 64;
    const int bm = blockIdx.y * 128;
    const int w = tid >> 5, lane = tid & 31;
    const int wm = (w & 3) * 32;
    const int wn = (w >> 2) * 32;
    const int qr = lane >> 2;
    const int qc = lane & 3;
    const int jj = lane >> 3, rr = lane & 7;

    float acc1[2][4][4], acc2[2][4][4];
    #pragma unroll
    for (int i = 0; i < 2; i++)
        #pragma unroll
        for (int j = 0; j < 4; j++)
            #pragma unroll
            for (int k = 0; k < 4; k++) { acc1[i][j][k] = 0.f; acc2[i][j][k] = 0.f; }

    const int nk = K >> 5;
    const int ra = tid >> 2;
    const int c4 = tid & 3;

    auto prefetch = [&](int ck, int buf) {
        const uint32_t sb = sbase + buf * (SM_WORDS * 4);
        #pragma unroll
        for (int i = 0; i < 2; i++) {
            const int r = ra + i * 64;
            const size_t go = (size_t)(bm + r) * K + ck * 32 + c4 * 8;
            cp_async16(sb + (SM_A_HI + r * HPITCH + c4 * 4) * 4, Ahi + go);
            cp_async16(sb + (SM_A_LO + r * HPITCH + c4 * 4) * 4, Alo + go);
        }
        {
            const int r = ra;
            const size_t go = (size_t)(bn + r) * K + ck * 32 + c4 * 8;
            cp_async16(sb + (SM_B_HI + r * HPITCH + c4 * 4) * 4, Whi + go);
            cp_async16(sb + (SM_B_LO + r * HPITCH + c4 * 4) * 4, Wlo + go);
        }
        cp_commit();
    };

    prefetch(0, 0);
    if (nk > 1) prefetch(1, 1);

    const int a_m  = ((jj & 1) << 3) + rr;
    const int a_kw = (jj >> 1) << 2;
    const int b_n  = rr;
    const int b_kw = jj << 2;

    int buf = 0;
    for (int ck = 0; ck < nk; ck++) {
        if (ck == nk - 1) cp_wait<0>(); else cp_wait<1>();
        __syncthreads();
        if (ck + 2 < nk) prefetch(ck + 2, (buf + 2) % NSTAGE);

        const uint32_t bufb = sbase + buf * (SM_WORDS * 4);

        uint32_t ah[2][2][4], al[2][2][4];
        #pragma unroll
        for (int mt = 0; mt < 2; mt++)
            #pragma unroll
            for (int ks = 0; ks < 2; ks++) {
                const uint32_t wo = (uint32_t)((wm + mt * 16 + a_m) * HPITCH + ks * 8 + a_kw);
                ldmatrix_x4(ah[mt][ks][0], ah[mt][ks][1], ah[mt][ks][2], ah[mt][ks][3],
                            bufb + (SM_A_HI + wo) * 4);
                ldmatrix_x4(al[mt][ks][0], al[mt][ks][1], al[mt][ks][2], al[mt][ks][3],
                            bufb + (SM_A_LO + wo) * 4);
            }

        #pragma unroll
        for (int nt = 0; nt < 4; nt++) {
            const uint32_t wo = (uint32_t)((wn + nt * 8 + b_n) * HPITCH + b_kw);
            uint32_t bh[2][2], bl[2][2];
            ldmatrix_x4(bh[0][0], bh[0][1], bh[1][0], bh[1][1], bufb + (SM_B_HI + wo) * 4);
            #pragma unroll
            for (int ks = 0; ks < 2; ks++) {
                #pragma unroll
                for (int mt = 0; mt < 2; mt++)
                    mma_f16(acc1[mt][nt], ah[mt][ks][0], ah[mt][ks][1],
                            ah[mt][ks][2], ah[mt][ks][3], bh[ks][0], bh[ks][1]);
                #pragma unroll
                for (int mt = 0; mt < 2; mt++)
                    mma_f16(acc2[mt][nt], al[mt][ks][0], al[mt][ks][1],
                            al[mt][ks][2], al[mt][ks][3], bh[ks][0], bh[ks][1]);
            }
            ldmatrix_x4(bl[0][0], bl[0][1], bl[1][0], bl[1][1], bufb + (SM_B_LO + wo) * 4);
            #pragma unroll
            for (int ks = 0; ks < 2; ks++)
                #pragma unroll
                for (int mt = 0; mt < 2; mt++)
                    mma_f16(acc2[mt][nt], ah[mt][ks][0], ah[mt][ks][1],
                            ah[mt][ks][2], ah[mt][ks][3], bl[ks][0], bl[ks][1]);
        }
        buf++; if (buf == NSTAGE) buf = 0;
    }

    // ---- epilogue ----
    #pragma unroll
    for (int nt = 0; nt < 4; nt++) {
        const int col = bn + wn + nt * 8 + qc * 2;
        const float b0 = bias[col], b1 = bias[col + 1];
        #pragma unroll
        for (int mt = 0; mt < 2; mt++) {
            const int row = bm + wm + mt * 16 + qr;
            float2 v0, v1;
            v0.x = fmaf(acc2[mt][nt][0], LO_INV, acc1[mt][nt][0]) + b0;
            v0.y = fmaf(acc2[mt][nt][1], LO_INV, acc1[mt][nt][1]) + b1;
            v1.x = fmaf(acc2[mt][nt][2], LO_INV, acc1[mt][nt][2]) + b0;
            v1.y = fmaf(acc2[mt][nt][3], LO_INV, acc1[mt][nt][3]) + b1;
            if (RELU) {
                v0.x = fmaxf(v0.x, 0.f); v0.y = fmaxf(v0.y, 0.f);
                v1.x = fmaxf(v1.x, 0.f); v1.y = fmaxf(v1.y, 0.f);
            }
            if (OUTF32) {
                *(float2*)(Cf + (size_t)row * N + col) = v0;
                *(float2*)(Cf + (size_t)(row + 8) * N + col) = v1;
            } else {
                uint32_t h, l;
                split_pack(v0.x, v0.y, h, l);
                ((uint32_t*)Chi)[((size_t)row * N + col) >> 1] = h;
                ((uint32_t*)Clo)[((size_t)row * N + col) >> 1] = l;
                split_pack(v1.x, v1.y, h, l);
                ((uint32_t*)Chi)[((size_t)(row + 8) * N + col) >> 1] = h;
                ((uint32_t*)Clo)[((size_t)(row + 8) * N + col) >> 1] = l;
            }
        }
    }
}

// ---------------- SIMT fp32 GEMM (N=32 latent layer) ----------------
template<int BM, int BN, int BK, int TM, int TN, bool RELU>
__global__ void __launch_bounds__((BM/TM)*(BN/TN))
gemm_nt_kernel(const float* __restrict__ A, const float* __restrict__ W,
               const float* __restrict__ bias, float* __restrict__ C,
               int M, int N, int K)
{
    constexpr int THREADS = (BM/TM)*(BN/TN);
    __shared__ float As[BK][BM];
    __shared__ float Ws[BK][BN];

    const int bm = blockIdx.y * BM;
    const int bn = blockIdx.x * BN;
    const int tid = threadIdx.x;
    const int tn = (tid % (BN/TN)) * TN;
    const int tm = (tid / (BN/TN)) * TM;

    float acc[TM][TN];
    #pragma unroll
    for (int i = 0; i < TM; i++)
        #pragma unroll
        for (int j = 0; j < TN; j++) acc[i][j] = 0.f;

    for (int k0 = 0; k0 < K; k0 += BK) {
        constexpr int A_LOADS = (BM*BK) / (4*THREADS);
        #pragma unroll
        for (int i = 0; i < A_LOADS; i++) {
            int idx = (tid + i*THREADS) * 4;
            int r = idx / BK, c = idx % BK;
            float4 v = *(const float4*)(A + (size_t)(bm + r)*K + k0 + c);
            As[c+0][r] = v.x; As[c+1][r] = v.y; As[c+2][r] = v.z; As[c+3][r] = v.w;
        }
        constexpr int W_LOADS = (BN*BK) / (4*THREADS);
        #pragma unroll
        for (int i = 0; i < W_LOADS; i++) {
            int idx = (tid + i*THREADS) * 4;
            int r = idx / BK, c = idx % BK;
            float4 v = *(const float4*)(W + (size_t)(bn + r)*K + k0 + c);
            Ws[c+0][r] = v.x; Ws[c+1][r] = v.y; Ws[c+2][r] = v.z; Ws[c+3][r] = v.w;
        }
        __syncthreads();

        #pragma unroll
        for (int k = 0; k < BK; k++) {
            float ar[TM], wr[TN];
            #pragma unroll
            for (int i = 0; i < TM; i += 4) {
                float4 v = *(const float4*)(&As[k][tm + i]);
                ar[i+0] = v.x; ar[i+1] = v.y; ar[i+2] = v.z; ar[i+3] = v.w;
            }
            #pragma unroll
            for (int j = 0; j < TN; j += 4) {
                float4 v = *(const float4*)(&Ws[k][tn + j]);
                wr[j+0] = v.x; wr[j+1] = v.y; wr[j+2] = v.z; wr[j+3] = v.w;
            }
            #pragma unroll
            for (int i = 0; i < TM; i++)
                #pragma unroll
                for (int j = 0; j < TN; j++)
                    acc[i][j] = fmaf(ar[i], wr[j], acc[i][j]);
        }
        __syncthreads();
    }

    #pragma unroll
    for (int i = 0; i < TM; i++)
        #pragma unroll
        for (int j = 0; j < TN; j++) {
            float v = acc[i][j] + bias[bn + tn + j];
            if (RELU) v = fmaxf(v, 0.f);
            C[(size_t)(bm + tm + i)*N + bn + tn + j] = v;
        }
}

// ---------------- fused residual-VQ kernel: 512 threads, 2 rows per step ----------------
__global__ void __launch_bounds__(2 * NE)
vq_kernel(const float* __restrict__ latent,
          const float* __restrict__ cb0, const float* __restrict__ cb1,
          const float* __restrict__ cb2,
          __half* __restrict__ xq_hi, __half* __restrict__ xq_lo,
          float* __restrict__ out_idx, float* __restrict__ out_oh,
          float* __restrict__ out_logits,
          int rows_per_block)
{
    extern __shared__ float smf[];
    float* cbs    = smf;                       // NQ*NE*CBPAD
    float* cnorm  = cbs + NQ*NE*CBPAD;         // NQ*NE
    float* resid  = cnorm + NQ*NE;             // 2*ED
    float* xqrow  = resid + 2*ED;              // 2*ED
    float* warp_v = xqrow + 2*ED;              // 16
    int*   warp_i = (int*)(warp_v + 16);       // 16
    int*   s_best = warp_i + 16;               // 2

    const int t = threadIdx.x;
    const int h = t >> 8;          // which row of the pair
    const int lt = t & 255;        // index within half
    const int wid_l = lt >> 5;     // warp within half (0..7)
    const int lane = t & 31;

    const float* srcs[NQ] = {cb0, cb1, cb2};
    for (int q = 0; q < NQ; q++)
        for (int i = t; i < NE*ED; i += 512) {
            int r = i / ED, c = i % ED;
            cbs[(q*NE + r)*CBPAD + c] = srcs[q][i];
        }
    __syncthreads();
    for (int i = t; i < NQ*NE; i += 512) {
        const float* row = &cbs[i*CBPAD];
        float s = 0.f;
        #pragma unroll
        for (int k = 0; k < ED; k++) s = fmaf(row[k], row[k], s);
        cnorm[i] = s;
    }
    __syncthreads();

    float loss_acc = 0.f;
    const int row0 = blockIdx.x * rows_per_block;
    const int row1 = min(row0 + rows_per_block, MROWS);

    for (int rb = row0; rb < row1; rb += 2) {
        const int r = rb + h;
        if (lt < ED) { resid[h*ED + lt] = latent[(size_t)r*ED + lt]; xqrow[h*ED + lt] = 0.f; }
        __syncthreads();

        for (int q = 0; q < NQ; q++) {
            const float* crow = &cbs[(q*NE + lt)*CBPAD];
            const float* rres = &resid[h*ED];
            float dot = 0.f, rn = 0.f;
            #pragma unroll
            for (int k = 0; k < ED; k++) {
                float rv = rres[k];
                dot = fmaf(rv, crow[k], dot);
                rn  = fmaf(rv, rv, rn);
            }
            float d = rn + cnorm[q*NE + lt] - 2.f*dot;
            out_logits[((size_t)r*NQ + q)*NE + lt] = d;

            float bv = d; int bi = lt;
            #pragma unroll
            for (int o = 16; o; o >>= 1) {
                float ov = __shfl_xor_sync(0xffffffffu, bv, o);
                int   oi = __shfl_xor_sync(0xffffffffu, bi, o);
                if (ov < bv || (ov == bv && oi < bi)) { bv = ov; bi = oi; }
            }
            if (lane == 0) { warp_v[h*8 + wid_l] = bv; warp_i[h*8 + wid_l] = bi; }
            __syncthreads();
            if (lt < 8) {
                bv = warp_v[h*8 + lt]; bi = warp_i[h*8 + lt];
                #pragma unroll
                for (int o = 4; o; o >>= 1) {
                    float ov = __shfl_xor_sync(0xffu, bv, o, 8);
                    int   oi = __shfl_xor_sync(0xffu, bi, o, 8);
                    if (ov < bv || (ov == bv && oi < bi)) { bv = ov; bi = oi; }
                }
                if (lt == 0) s_best[h] = bi;
            }
            __syncthreads();
            const int best = s_best[h];

            out_oh[((size_t)r*NQ + q)*NE + lt] = (lt == best) ? 1.f : 0.f;
            if (lt == 0) out_idx[(size_t)r*NQ + q] = (float)best;

            if (lt < 32) {
                float c  = cbs[(q*NE + best)*CBPAD + lt];
                float rv = resid[h*ED + lt];
                float diff = c - rv;
                float xres = rv + diff;
                float sq = diff*diff;
                #pragma unroll
                for (int o = 16; o; o >>= 1) sq += __shfl_xor_sync(0xffffffffu, sq, o);
                if (lt == 0) loss_acc += sq;
                resid[h*ED + lt] = rv - xres;
                xqrow[h*ED + lt] += xres;
            }
            __syncthreads();
        }
        if (lt < ED/2) {
            float x0 = xqrow[h*ED + 2*lt], x1 = xqrow[h*ED + 2*lt + 1];
            uint32_t hh, ll;
            split_pack(x0, x1, hh, ll);
            ((uint32_t*)xq_hi)[(size_t)r * (ED/2) + lt] = hh;
            ((uint32_t*)xq_lo)[(size_t)r * (ED/2) + lt] = ll;
        }
        __syncthreads();
    }
    if (lt == 0) atomicAdd(&g_loss, loss_acc);
}

__global__ void zero_loss_kernel() { g_loss = 0.f; }

__global__ void finalize_kernel(float* __restrict__ loss_out)
{
    loss_out[0] = g_loss * (1.25f / (3.0f * (float)MROWS * (float)ED));
}

// ---------------- launch ----------------
extern "C" void kernel_launch(void* const* d_in, const int* in_sizes, int n_in,
                              void* d_out, int out_size)
{
    const float* x   = (const float*)d_in[0];
    const float* ew[4] = {(const float*)d_in[1], (const float*)d_in[3],
                          (const float*)d_in[5], (const float*)d_in[7]};
    const float* eb[4] = {(const float*)d_in[2], (const float*)d_in[4],
                          (const float*)d_in[6], (const float*)d_in[8]};
    const float* dw[4] = {(const float*)d_in[9],  (const float*)d_in[11],
                          (const float*)d_in[13], (const float*)d_in[15]};
    const float* db[4] = {(const float*)d_in[10], (const float*)d_in[12],
                          (const float*)d_in[14], (const float*)d_in[16]};
    const float* cb0 = (const float*)d_in[17];
    const float* cb1 = (const float*)d_in[18];
    const float* cb2 = (const float*)d_in[19];
    float* out = (float*)d_out;

    float *h2f, *lat;
    cudaGetSymbolAddress((void**)&h2f, g_h2f);
    cudaGetSymbolAddress((void**)&lat, g_lat);
    __half *xhi, *xlo, *h0hi, *h0lo, *h1hi, *h1lo, *xqhi, *xqlo;
    __half *g0hi, *g0lo, *g1hi, *g1lo, *g2hi, *g2lo, *whi, *wlo;
    cudaGetSymbolAddress((void**)&xhi,  g_x_hi);  cudaGetSymbolAddress((void**)&xlo,  g_x_lo);
    cudaGetSymbolAddress((void**)&h0hi, g_h0_hi); cudaGetSymbolAddress((void**)&h0lo, g_h0_lo);
    cudaGetSymbolAddress((void**)&h1hi, g_h1_hi); cudaGetSymbolAddress((void**)&h1lo, g_h1_lo);
    cudaGetSymbolAddress((void**)&xqhi, g_xq_hi); cudaGetSymbolAddress((void**)&xqlo, g_xq_lo);
    cudaGetSymbolAddress((void**)&g0hi, g_g0_hi); cudaGetSymbolAddress((void**)&g0lo, g_g0_lo);
    cudaGetSymbolAddress((void**)&g1hi, g_g1_hi); cudaGetSymbolAddress((void**)&g1lo, g_g1_lo);
    cudaGetSymbolAddress((void**)&g2hi, g_g2_hi); cudaGetSymbolAddress((void**)&g2lo, g_g2_lo);
    cudaGetSymbolAddress((void**)&whi,  g_w_hi);  cudaGetSymbolAddress((void**)&wlo,  g_w_lo);

    const size_t OFF_OUT  = 0;
    const size_t OFF_LOSS = (size_t)MROWS * 1024;
    const size_t OFF_IDX  = OFF_LOSS + 1;
    const size_t OFF_OH   = OFF_IDX + (size_t)MROWS * NQ;
    const size_t OFF_LG   = OFF_OH  + (size_t)MROWS * NQ * NE;

    cudaFuncSetAttribute(gemm_split_kernel<true,false>, cudaFuncAttributeMaxDynamicSharedMemorySize, SMEM_BYTES_GEMM);
    cudaFuncSetAttribute(gemm_split_kernel<true,true>,  cudaFuncAttributeMaxDynamicSharedMemorySize, SMEM_BYTES_GEMM);
    cudaFuncSetAttribute(gemm_split_kernel<false,true>, cudaFuncAttributeMaxDynamicSharedMemorySize, SMEM_BYTES_GEMM);

    const int MT = MROWS / 128;
    auto splitN = [](int n) { return (n / 4 + 255) / 256; };

    // pre-split inputs + weights
    split_kernel<<<splitN(MROWS*1024), 256>>>(x, xhi, xlo, MROWS*1024/4);
    split_kernel<<<splitN(512*1024), 256>>>(ew[0], whi + WOFF0, wlo + WOFF0, 512*1024/4);
    split_kernel<<<splitN(256*512),  256>>>(ew[1], whi + WOFF1, wlo + WOFF1, 256*512/4);
    split_kernel<<<splitN(128*256),  256>>>(ew[2], whi + WOFF2, wlo + WOFF2, 128*256/4);
    split_kernel<<<splitN(128*32),   256>>>(dw[0], whi + WOFF3, wlo + WOFF3, 128*32/4);
    split_kernel<<<splitN(256*128),  256>>>(dw[1], whi + WOFF4, wlo + WOFF4, 256*128/4);
    split_kernel<<<splitN(512*256),  256>>>(dw[2], whi + WOFF5, wlo + WOFF5, 512*256/4);
    split_kernel<<<splitN(1024*512), 256>>>(dw[3], whi + WOFF6, wlo + WOFF6, 1024*512/4);

    // encoder
    gemm_split_kernel<true,false><<<dim3(8, MT), 256, SMEM_BYTES_GEMM>>>(
        xhi, xlo, whi + WOFF0, wlo + WOFF0, eb[0], h0hi, h0lo, nullptr, 512, 1024);
    gemm_split_kernel<true,false><<<dim3(4, MT), 256, SMEM_BYTES_GEMM>>>(
        h0hi, h0lo, whi + WOFF1, wlo + WOFF1, eb[1], h1hi, h1lo, nullptr, 256, 512);
    gemm_split_kernel<true,true><<<dim3(2, MT), 256, SMEM_BYTES_GEMM>>>(
        h1hi, h1lo, whi + WOFF2, wlo + WOFF2, eb[2], nullptr, nullptr, h2f, 128, 256);
    gemm_nt_kernel<128, 32,16,8,4,false><<<dim3(1, MT), 128>>>(h2f, ew[3], eb[3], lat, MROWS, 32, 128);

    // residual VQ (512 threads, 2 rows per step)
    zero_loss_kernel<<<1,1>>>();
    const size_t vq_smem = (size_t)(NQ*NE*CBPAD + NQ*NE + 4*ED + 16)*4 + 16*4 + 8;
    cudaFuncSetAttribute(vq_kernel, cudaFuncAttributeMaxDynamicSharedMemorySize, (int)vq_smem);
    vq_kernel<<<MROWS/32, 2*NE, vq_smem>>>(lat, cb0, cb1, cb2, xqhi, xqlo,
                                           out + OFF_IDX, out + OFF_OH, out + OFF_LG, 32);
    finalize_kernel<<<1,1>>>(out + OFF_LOSS);

    // decoder (all full precision)
    gemm_split_kernel<true,false><<<dim3(2,  MT), 256, SMEM_BYTES_GEMM>>>(
        xqhi, xqlo, whi + WOFF3, wlo + WOFF3, db[0], g0hi, g0lo, nullptr, 128, 32);
    gemm_split_kernel<true,false><<<dim3(4,  MT), 256, SMEM_BYTES_GEMM>>>(
        g0hi, g0lo, whi + WOFF4, wlo + WOFF4, db[1], g1hi, g1lo, nullptr, 256, 128);
    gemm_split_kernel<true,false><<<dim3(8,  MT), 256, SMEM_BYTES_GEMM>>>(
        g1hi, g1lo, whi + WOFF5, wlo + WOFF5, db[2], g2hi, g2lo, nullptr, 512, 256);
    gemm_split_kernel<false,true><<<dim3(16, MT), 256, SMEM_BYTES_GEMM>>>(
        g2hi, g2lo, whi + WOFF6, wlo + WOFF6, db[3], nullptr, nullptr, out + OFF_OUT, 1024, 512);
}